// round 1
// baseline (speedup 1.0000x reference)
#include <cuda_runtime.h>

#define NB 16
#define CIN 512
#define COUT 256
#define HH 32
#define WW 32
#define EPSV 1e-5f
#define CK 8
#define XSTR 35   // 34 cols needed; stride 35 => conflict-free LDS pattern

// Scratch (static device globals: no allocations allowed)
__device__ float g_scratch[4ull * NB * COUT * HH * WW];   // [conv][n][c][32][32]  (~67 MB)
__device__ float g_wt[4ull * CIN * 9 * COUT];             // [conv][ci][tap(3x3)][co] (~19 MB)
__device__ float g_part[16 * 64 * 64 * 2];                // [cb16][spatialblk64][ch64][{s,s2}]
__device__ float g_scale[COUT];
__device__ float g_shift[COUT];

// ---------------------------------------------------------------------------
// Weight transpose/pad: w_k[co][ci][kh][kw] -> g_wt[conv][ci][dy*3+dx][co]
// Unused taps zero-filled (never read by the main loop anyway).
// ---------------------------------------------------------------------------
__global__ void prep_weights(const float* __restrict__ w1, const float* __restrict__ w2,
                             const float* __restrict__ w3, const float* __restrict__ w4) {
    const int total = 4 * CIN * 9 * COUT;
    for (int idx = blockIdx.x * blockDim.x + threadIdx.x; idx < total;
         idx += gridDim.x * blockDim.x) {
        int co   = idx & 255;
        int t    = idx >> 8;
        int tap  = t % 9;
        int t2   = t / 9;
        int ci   = t2 & (CIN - 1);
        int conv = t2 >> 9;
        int dy = tap / 3, dx = tap % 3;
        int kh = 3 - (conv & 1);          // conv0:3 conv1:2 conv2:3 conv3:2
        int kw = 3 - ((conv >> 1) & 1);   // conv0:3 conv1:3 conv2:2 conv3:2
        float v = 0.f;
        if (dy < kh && dx < kw) {
            const float* w = (conv == 0) ? w1 : (conv == 1) ? w2 : (conv == 2) ? w3 : w4;
            v = w[((co * CIN + ci) * kh + dy) * kw + dx];
        }
        g_wt[idx] = v;
    }
}

// ---------------------------------------------------------------------------
// Main conv body. Block: 64 unified channels x (n, 8 rows x 32 cols).
// Thread: 8 channels x 8 pixels register tile.
// tid: g = tid>>5 (channel group), lane: r = lane>>2 (row), cg = lane&3 (col group)
// ---------------------------------------------------------------------------
template <int CONV, int KH, int KW>
__device__ __forceinline__ void conv_body(
    const float* __restrict__ x, const float* __restrict__ bias,
    float (*Xs)[10][XSTR], float (*Ws)[9][64]) {

    const int n   = blockIdx.z;
    const int cby = blockIdx.y & 3;   // 0..3 within this conv
    const int rb  = blockIdx.x;       // 0..3
    const int c0  = cby * 64;
    const int R0  = rb * 8;
    const int tid  = threadIdx.x;
    const int g    = tid >> 5;
    const int lane = tid & 31;
    const int r    = lane >> 2;
    const int cg   = lane & 3;

    float acc[8][8];
#pragma unroll
    for (int c = 0; c < 8; c++) {
        float bv = bias[c0 + g * 8 + c];
#pragma unroll
        for (int p = 0; p < 8; p++) acc[c][p] = bv;
    }

    const float* xbase = x + (size_t)n * CIN * HH * WW;
    const float* wtb   = g_wt + ((size_t)CONV * CIN) * 9 * COUT;

    for (int ci0 = 0; ci0 < CIN; ci0 += CK) {
        __syncthreads();
        // Stage x: CK channels, rows R0-1..R0+8 (10), cols -1..32 (34), zero-padded
        for (int idx = tid; idx < CK * 10 * 34; idx += 256) {
            int col = idx % 34;
            int t2  = idx / 34;
            int row = t2 % 10;
            int ci  = t2 / 10;
            int ir = R0 - 1 + row;
            int ic = col - 1;
            float v = 0.f;
            if (ir >= 0 && ir < HH && (unsigned)ic < (unsigned)WW)
                v = xbase[(size_t)(ci0 + ci) * HH * WW + ir * WW + ic];
            Xs[ci][row][col] = v;
        }
        // Stage weights: [ci][tap][64]
        for (int idx = tid; idx < CK * 9 * 64; idx += 256) {
            int co  = idx & 63;
            int t2  = idx >> 6;
            int tap = t2 % 9;
            int ci  = t2 / 9;
            Ws[ci][tap][co] = wtb[((size_t)(ci0 + ci) * 9 + tap) * COUT + c0 + co];
        }
        __syncthreads();

#pragma unroll 1
        for (int ci = 0; ci < CK; ci++) {
            float xr[KH][KW + 7];
#pragma unroll
            for (int dy = 0; dy < KH; dy++)
#pragma unroll
                for (int m = 0; m < KW + 7; m++)
                    xr[dy][m] = Xs[ci][r + dy][cg * 8 + m];
#pragma unroll
            for (int dy = 0; dy < KH; dy++) {
#pragma unroll
                for (int dx = 0; dx < KW; dx++) {
                    float4 wa = *(const float4*)&Ws[ci][dy * 3 + dx][g * 8];
                    float4 wb = *(const float4*)&Ws[ci][dy * 3 + dx][g * 8 + 4];
                    float wv[8] = {wa.x, wa.y, wa.z, wa.w, wb.x, wb.y, wb.z, wb.w};
#pragma unroll
                    for (int c = 0; c < 8; c++)
#pragma unroll
                        for (int p = 0; p < 8; p++)
                            acc[c][p] += wv[c] * xr[dy][p + dx];
                }
            }
        }
    }

    // Store conv output to scratch [conv][n][c][i][j]
    {
        float* sc = g_scratch +
            ((((size_t)(CONV * NB + n) * COUT + c0 + g * 8) * HH + (R0 + r)) * WW + cg * 8);
#pragma unroll
        for (int c = 0; c < 8; c++) {
            *(float4*)(sc + (size_t)c * HH * WW)     = make_float4(acc[c][0], acc[c][1], acc[c][2], acc[c][3]);
            *(float4*)(sc + (size_t)c * HH * WW + 4) = make_float4(acc[c][4], acc[c][5], acc[c][6], acc[c][7]);
        }
    }
    // Deterministic BN partial sums: warp covers all 32 pixel groups of this block
    {
        const int cbG = CONV * 4 + cby;
#pragma unroll
        for (int c = 0; c < 8; c++) {
            float s = 0.f, q = 0.f;
#pragma unroll
            for (int p = 0; p < 8; p++) { float v = acc[c][p]; s += v; q += v * v; }
#pragma unroll
            for (int off = 16; off > 0; off >>= 1) {
                s += __shfl_xor_sync(0xffffffffu, s, off);
                q += __shfl_xor_sync(0xffffffffu, q, off);
            }
            if (lane == 0) {
                size_t pi = ((size_t)(cbG * 64 + n * 4 + rb) * 64 + g * 8 + c) * 2;
                g_part[pi]     = s;
                g_part[pi + 1] = q;
            }
        }
    }
}

__global__ __launch_bounds__(256, 1)
void conv_all(const float* __restrict__ x,
              const float* __restrict__ b1, const float* __restrict__ b2,
              const float* __restrict__ b3, const float* __restrict__ b4) {
    __shared__ float Xs[CK][10][XSTR];
    __shared__ float Ws[CK][9][64];
    switch (blockIdx.y >> 2) {
        case 0: conv_body<0, 3, 3>(x, b1, Xs, Ws); break;
        case 1: conv_body<1, 2, 3>(x, b2, Xs, Ws); break;
        case 2: conv_body<2, 3, 2>(x, b3, Xs, Ws); break;
        default: conv_body<3, 2, 2>(x, b4, Xs, Ws); break;
    }
}

// ---------------------------------------------------------------------------
// Combine partials -> per-final-channel scale/shift (gamma,beta folded in)
// ---------------------------------------------------------------------------
__global__ void stats_k(const float* __restrict__ gamma, const float* __restrict__ beta) {
    int c = threadIdx.x;  // 256 threads
    float S = 0.f, S2 = 0.f;
#pragma unroll 1
    for (int conv = 0; conv < 4; conv++) {
        int cb    = conv * 4 + (c >> 6);
        int chIdx = c & 63;
        for (int sb = 0; sb < 64; sb++) {
            size_t pi = ((size_t)(cb * 64 + sb) * 64 + chIdx) * 2;
            S  += g_part[pi];
            S2 += g_part[pi + 1];
        }
    }
    const float inv = 1.f / 65536.f;  // N * 64 * 64
    float mean = S * inv;
    float var  = S2 * inv - mean * mean;
    float rstd = rsqrtf(var + EPSV);
    float sc   = gamma[c] * rstd;
    g_scale[c] = sc;
    g_shift[c] = beta[c] - mean * sc;
}

// ---------------------------------------------------------------------------
// Normalize + ReLU + pixel-shuffle interleave to out[n][c][2H][2W]
// y[2i,2j]=conv0, y[2i+1,2j]=conv1, y[2i,2j+1]=conv2, y[2i+1,2j+1]=conv3
// ---------------------------------------------------------------------------
__global__ void apply_k(float* __restrict__ out) {
    int t = blockIdx.x * blockDim.x + threadIdx.x;
    int base = t * 4;
    if (base >= NB * COUT * 64 * 64) return;
    int J0 = base & 63;
    int I  = (base >> 6) & 63;
    int c  = (base >> 12) & 255;
    int n  = base >> 20;
    int i  = I >> 1;
    int pr = I & 1;
    float sc = g_scale[c];
    float sh = g_shift[c];
    float v[4];
#pragma unroll
    for (int e = 0; e < 4; e++) {
        int J    = J0 + e;
        int conv = pr + ((J & 1) << 1);
        int j    = J >> 1;
        float o = g_scratch[((((size_t)conv * NB + n) * COUT + c) * HH + i) * WW + j];
        float y = o * sc + sh;
        v[e] = y > 0.f ? y : 0.f;
    }
    *(float4*)(out + base) = make_float4(v[0], v[1], v[2], v[3]);
}

// ---------------------------------------------------------------------------
extern "C" void kernel_launch(void* const* d_in, const int* in_sizes, int n_in,
                              void* d_out, int out_size) {
    const float* x     = (const float*)d_in[0];
    const float* w1    = (const float*)d_in[1];
    const float* b1    = (const float*)d_in[2];
    const float* w2    = (const float*)d_in[3];
    const float* b2    = (const float*)d_in[4];
    const float* w3    = (const float*)d_in[5];
    const float* b3    = (const float*)d_in[6];
    const float* w4    = (const float*)d_in[7];
    const float* b4    = (const float*)d_in[8];
    const float* gamma = (const float*)d_in[9];
    const float* beta  = (const float*)d_in[10];
    float* out = (float*)d_out;

    prep_weights<<<2048, 256>>>(w1, w2, w3, w4);
    dim3 grid(4, 16, 16);  // (rowblk, conv*4+cslice, n)
    conv_all<<<grid, 256>>>(x, b1, b2, b3, b4);
    stats_k<<<1, 256>>>(gamma, beta);
    apply_k<<<(NB * COUT * 64 * 64 / 4 + 255) / 256, 256>>>(out);
}

// round 2
// speedup vs baseline: 1.0019x; 1.0019x over previous
#include <cuda_runtime.h>

#define NB 16
#define CIN 512
#define COUT 256
#define HH 32
#define WW 32
#define EPSV 1e-5f
#define CK 8
#define XSTR 35   // 34 cols needed; stride 35 => conflict-free LDS pattern

// Scratch (static device globals: no allocations allowed)
__device__ float g_scratch[4ull * NB * COUT * HH * WW];   // [conv][n][c][32][32]  (~67 MB)
__device__ float g_wt[4ull * CIN * 9 * COUT];             // [conv][ci][tap(3x3)][co] (~19 MB)
__device__ float g_part[16 * 64 * 64 * 2];                // [cb16][spatialblk64][ch64][{s,s2}]
__device__ float g_scale[COUT];
__device__ float g_shift[COUT];

// ---------------------------------------------------------------------------
// Weight transpose/pad: w_k[co][ci][kh][kw] -> g_wt[conv][ci][dy*3+dx][co]
// Unused taps zero-filled (never read by the main loop anyway).
// ---------------------------------------------------------------------------
__global__ void prep_weights(const float* __restrict__ w1, const float* __restrict__ w2,
                             const float* __restrict__ w3, const float* __restrict__ w4) {
    const int total = 4 * CIN * 9 * COUT;
    for (int idx = blockIdx.x * blockDim.x + threadIdx.x; idx < total;
         idx += gridDim.x * blockDim.x) {
        int co   = idx & 255;
        int t    = idx >> 8;
        int tap  = t % 9;
        int t2   = t / 9;
        int ci   = t2 & (CIN - 1);
        int conv = t2 >> 9;
        int dy = tap / 3, dx = tap % 3;
        int kh = 3 - (conv & 1);          // conv0:3 conv1:2 conv2:3 conv3:2
        int kw = 3 - ((conv >> 1) & 1);   // conv0:3 conv1:3 conv2:2 conv3:2
        float v = 0.f;
        if (dy < kh && dx < kw) {
            const float* w = (conv == 0) ? w1 : (conv == 1) ? w2 : (conv == 2) ? w3 : w4;
            v = w[((co * CIN + ci) * kh + dy) * kw + dx];
        }
        g_wt[idx] = v;
    }
}

// ---------------------------------------------------------------------------
// Main conv body. Block: 64 unified channels x (n, 8 rows x 32 cols).
// Thread: 8 channels x 8 pixels register tile.
// tid: g = tid>>5 (channel group), lane: r = lane>>2 (row), cg = lane&3 (col group)
// ---------------------------------------------------------------------------
template <int CONV, int KH, int KW>
__device__ __forceinline__ void conv_body(
    const float* __restrict__ x, const float* __restrict__ bias,
    float (*Xs)[10][XSTR], float (*Ws)[9][64]) {

    const int n   = blockIdx.z;
    const int cby = blockIdx.y & 3;   // 0..3 within this conv
    const int rb  = blockIdx.x;       // 0..3
    const int c0  = cby * 64;
    const int R0  = rb * 8;
    const int tid  = threadIdx.x;
    const int g    = tid >> 5;
    const int lane = tid & 31;
    const int r    = lane >> 2;
    const int cg   = lane & 3;

    float acc[8][8];
#pragma unroll
    for (int c = 0; c < 8; c++) {
        float bv = bias[c0 + g * 8 + c];
#pragma unroll
        for (int p = 0; p < 8; p++) acc[c][p] = bv;
    }

    const float* xbase = x + (size_t)n * CIN * HH * WW;
    const float* wtb   = g_wt + ((size_t)CONV * CIN) * 9 * COUT;

    for (int ci0 = 0; ci0 < CIN; ci0 += CK) {
        __syncthreads();
        // Stage x: CK channels, rows R0-1..R0+8 (10), cols -1..32 (34), zero-padded
        for (int idx = tid; idx < CK * 10 * 34; idx += 256) {
            int col = idx % 34;
            int t2  = idx / 34;
            int row = t2 % 10;
            int ci  = t2 / 10;
            int ir = R0 - 1 + row;
            int ic = col - 1;
            float v = 0.f;
            if (ir >= 0 && ir < HH && (unsigned)ic < (unsigned)WW)
                v = xbase[(size_t)(ci0 + ci) * HH * WW + ir * WW + ic];
            Xs[ci][row][col] = v;
        }
        // Stage weights: [ci][tap][64]
        for (int idx = tid; idx < CK * 9 * 64; idx += 256) {
            int co  = idx & 63;
            int t2  = idx >> 6;
            int tap = t2 % 9;
            int ci  = t2 / 9;
            Ws[ci][tap][co] = wtb[((size_t)(ci0 + ci) * 9 + tap) * COUT + c0 + co];
        }
        __syncthreads();

#pragma unroll 1
        for (int ci = 0; ci < CK; ci++) {
            float xr[KH][KW + 7];
#pragma unroll
            for (int dy = 0; dy < KH; dy++)
#pragma unroll
                for (int m = 0; m < KW + 7; m++)
                    xr[dy][m] = Xs[ci][r + dy][cg * 8 + m];
#pragma unroll
            for (int dy = 0; dy < KH; dy++) {
#pragma unroll
                for (int dx = 0; dx < KW; dx++) {
                    float4 wa = *(const float4*)&Ws[ci][dy * 3 + dx][g * 8];
                    float4 wb = *(const float4*)&Ws[ci][dy * 3 + dx][g * 8 + 4];
                    float wv[8] = {wa.x, wa.y, wa.z, wa.w, wb.x, wb.y, wb.z, wb.w};
#pragma unroll
                    for (int c = 0; c < 8; c++)
#pragma unroll
                        for (int p = 0; p < 8; p++)
                            acc[c][p] += wv[c] * xr[dy][p + dx];
                }
            }
        }
    }

    // Store conv output to scratch [conv][n][c][i][j]
    {
        float* sc = g_scratch +
            ((((size_t)(CONV * NB + n) * COUT + c0 + g * 8) * HH + (R0 + r)) * WW + cg * 8);
#pragma unroll
        for (int c = 0; c < 8; c++) {
            *(float4*)(sc + (size_t)c * HH * WW)     = make_float4(acc[c][0], acc[c][1], acc[c][2], acc[c][3]);
            *(float4*)(sc + (size_t)c * HH * WW + 4) = make_float4(acc[c][4], acc[c][5], acc[c][6], acc[c][7]);
        }
    }
    // Deterministic BN partial sums: warp covers all 32 pixel groups of this block
    {
        const int cbG = CONV * 4 + cby;
#pragma unroll
        for (int c = 0; c < 8; c++) {
            float s = 0.f, q = 0.f;
#pragma unroll
            for (int p = 0; p < 8; p++) { float v = acc[c][p]; s += v; q += v * v; }
#pragma unroll
            for (int off = 16; off > 0; off >>= 1) {
                s += __shfl_xor_sync(0xffffffffu, s, off);
                q += __shfl_xor_sync(0xffffffffu, q, off);
            }
            if (lane == 0) {
                size_t pi = ((size_t)(cbG * 64 + n * 4 + rb) * 64 + g * 8 + c) * 2;
                g_part[pi]     = s;
                g_part[pi + 1] = q;
            }
        }
    }
}

__global__ __launch_bounds__(256, 1)
void conv_all(const float* __restrict__ x,
              const float* __restrict__ b1, const float* __restrict__ b2,
              const float* __restrict__ b3, const float* __restrict__ b4) {
    __shared__ float Xs[CK][10][XSTR];
    __shared__ float Ws[CK][9][64];
    switch (blockIdx.y >> 2) {
        case 0: conv_body<0, 3, 3>(x, b1, Xs, Ws); break;
        case 1: conv_body<1, 2, 3>(x, b2, Xs, Ws); break;
        case 2: conv_body<2, 3, 2>(x, b3, Xs, Ws); break;
        default: conv_body<3, 2, 2>(x, b4, Xs, Ws); break;
    }
}

// ---------------------------------------------------------------------------
// Combine partials -> per-final-channel scale/shift (gamma,beta folded in)
// ---------------------------------------------------------------------------
__global__ void stats_k(const float* __restrict__ gamma, const float* __restrict__ beta) {
    int c = threadIdx.x;  // 256 threads
    float S = 0.f, S2 = 0.f;
#pragma unroll 1
    for (int conv = 0; conv < 4; conv++) {
        int cb    = conv * 4 + (c >> 6);
        int chIdx = c & 63;
        for (int sb = 0; sb < 64; sb++) {
            size_t pi = ((size_t)(cb * 64 + sb) * 64 + chIdx) * 2;
            S  += g_part[pi];
            S2 += g_part[pi + 1];
        }
    }
    const float inv = 1.f / 65536.f;  // N * 64 * 64
    float mean = S * inv;
    float var  = S2 * inv - mean * mean;
    float rstd = rsqrtf(var + EPSV);
    float sc   = gamma[c] * rstd;
    g_scale[c] = sc;
    g_shift[c] = beta[c] - mean * sc;
}

// ---------------------------------------------------------------------------
// Normalize + ReLU + pixel-shuffle interleave to out[n][c][2H][2W]
// y[2i,2j]=conv0, y[2i+1,2j]=conv1, y[2i,2j+1]=conv2, y[2i+1,2j+1]=conv3
// ---------------------------------------------------------------------------
__global__ void apply_k(float* __restrict__ out) {
    int t = blockIdx.x * blockDim.x + threadIdx.x;
    int base = t * 4;
    if (base >= NB * COUT * 64 * 64) return;
    int J0 = base & 63;
    int I  = (base >> 6) & 63;
    int c  = (base >> 12) & 255;
    int n  = base >> 20;
    int i  = I >> 1;
    int pr = I & 1;
    float sc = g_scale[c];
    float sh = g_shift[c];
    float v[4];
#pragma unroll
    for (int e = 0; e < 4; e++) {
        int J    = J0 + e;
        int conv = pr + ((J & 1) << 1);
        int j    = J >> 1;
        float o = g_scratch[((((size_t)conv * NB + n) * COUT + c) * HH + i) * WW + j];
        float y = o * sc + sh;
        v[e] = y > 0.f ? y : 0.f;
    }
    *(float4*)(out + base) = make_float4(v[0], v[1], v[2], v[3]);
}

// ---------------------------------------------------------------------------
extern "C" void kernel_launch(void* const* d_in, const int* in_sizes, int n_in,
                              void* d_out, int out_size) {
    const float* x     = (const float*)d_in[0];
    const float* w1    = (const float*)d_in[1];
    const float* b1    = (const float*)d_in[2];
    const float* w2    = (const float*)d_in[3];
    const float* b2    = (const float*)d_in[4];
    const float* w3    = (const float*)d_in[5];
    const float* b3    = (const float*)d_in[6];
    const float* w4    = (const float*)d_in[7];
    const float* b4    = (const float*)d_in[8];
    const float* gamma = (const float*)d_in[9];
    const float* beta  = (const float*)d_in[10];
    float* out = (float*)d_out;

    prep_weights<<<2048, 256>>>(w1, w2, w3, w4);
    dim3 grid(4, 16, 16);  // (rowblk, conv*4+cslice, n)
    conv_all<<<grid, 256>>>(x, b1, b2, b3, b4);
    stats_k<<<1, 256>>>(gamma, beta);
    apply_k<<<(NB * COUT * 64 * 64 / 4 + 255) / 256, 256>>>(out);
}

// round 4
// speedup vs baseline: 3.0916x; 3.0858x over previous
#include <cuda_runtime.h>
#include <cuda_bf16.h>
#include <cstdint>

#define NB 16
#define CIN 512
#define COUT 256
#define HH 32
#define WW 32
#define EPSV 1e-5f

__device__ __align__(16) __nv_bfloat16 g_Ah[9ull * 16384 * 512];
__device__ __align__(16) __nv_bfloat16 g_Al[9ull * 16384 * 512];
__device__ __align__(16) __nv_bfloat16 g_Bh[36ull * 256 * 512];
__device__ __align__(16) __nv_bfloat16 g_Bl[36ull * 256 * 512];
__device__ float g_scratch[4ull * NB * COUT * HH * WW]; // [conv][n][c][1024]
__device__ float g_scale[COUT];
__device__ float g_shift[COUT];

__constant__ int c_taps[4][9] = {
    {0,1,2,3,4,5,6,7,8}, {0,1,2,3,4,5,0,0,0}, {0,1,3,4,6,7,0,0,0}, {0,1,3,4,0,0,0,0,0}};
__constant__ int c_ntaps[4] = {9, 6, 6, 4};

__device__ __forceinline__ uint32_t smem_u32(const void* p) {
    uint32_t a;
    asm("{ .reg .u64 t; cvta.to.shared.u64 t, %1; cvt.u32.u64 %0, t; }" : "=r"(a) : "l"(p));
    return a;
}

#define ROWB  144u    // 64 bf16 (128B) + 16B pad: 16B-aligned, conflict-free ldmatrix
#define TILEB 18432u  // 128 rows * 144B
#define STAGEB 73728u // Ah, Al, Bh, Bl tiles
#define SMEM_SZ (2u * STAGEB)

__device__ __forceinline__ void ldsm4(uint32_t& r0, uint32_t& r1, uint32_t& r2, uint32_t& r3,
                                      uint32_t a) {
    asm volatile("ldmatrix.sync.aligned.m8n8.x4.shared.b16 {%0,%1,%2,%3}, [%4];"
                 : "=r"(r0), "=r"(r1), "=r"(r2), "=r"(r3) : "r"(a));
}
__device__ __forceinline__ void mma_bf16(float* d, const uint32_t* a, uint32_t b0, uint32_t b1) {
    asm volatile(
        "mma.sync.aligned.m16n8k16.row.col.f32.bf16.bf16.f32 "
        "{%0,%1,%2,%3}, {%4,%5,%6,%7}, {%8,%9}, {%0,%1,%2,%3};"
        : "+f"(d[0]), "+f"(d[1]), "+f"(d[2]), "+f"(d[3])
        : "r"(a[0]), "r"(a[1]), "r"(a[2]), "r"(a[3]), "r"(b0), "r"(b1));
}

// ---------------------------------------------------------------------------
__global__ void prep_w(const float* __restrict__ w1, const float* __restrict__ w2,
                       const float* __restrict__ w3, const float* __restrict__ w4) {
    const int total = 36 * 256 * 512;
    for (int idx = blockIdx.x * blockDim.x + threadIdx.x; idx < total;
         idx += gridDim.x * blockDim.x) {
        int ci = idx & 511, co = (idx >> 9) & 255;
        int tap = (idx >> 17) % 9, conv = idx / (9 << 17);
        int dy = tap / 3, dx = tap % 3;
        int kh = 3 - (conv & 1), kw = 3 - ((conv >> 1) & 1);
        float v = 0.f;
        if (dy < kh && dx < kw) {
            const float* w = (conv == 0) ? w1 : (conv == 1) ? w2 : (conv == 2) ? w3 : w4;
            v = w[((co * CIN + ci) * kh + dy) * kw + dx];
        }
        __nv_bfloat16 hi = __float2bfloat16(v);
        g_Bh[idx] = hi;
        g_Bl[idx] = __float2bfloat16(v - __bfloat162float(hi));
    }
}

// im2col: x -> K-major bf16 hi/lo [tap][p][ci]; grid (8, 16, 9), 256 thr
__global__ void prep_a(const float* __restrict__ x) {
    __shared__ float S[128][33];
    const int rb = blockIdx.x, n = blockIdx.y, tap = blockIdx.z;
    const int dy = tap / 3, dx = tap % 3;
    const int tid = threadIdx.x;
    const size_t outbase = (size_t)tap * 16384 * 512 + ((size_t)n * 1024 + rb * 128) * 512;
    for (int cic = 0; cic < 16; cic++) {
        const int ci0 = cic * 32;
        __syncthreads();
#pragma unroll
        for (int k = 0; k < 16; k++) {
            int idx = tid + k * 256;
            int ci = idx >> 7, pl = idx & 127;
            int i = rb * 4 + (pl >> 5), j = pl & 31;
            int ii = i - 1 + dy, jj = j - 1 + dx;
            float v = 0.f;
            if (ii >= 0 && ii < HH && (unsigned)jj < (unsigned)WW)
                v = x[(((size_t)n * CIN + ci0 + ci) * HH + ii) * WW + jj];
            S[pl][ci] = v;
        }
        __syncthreads();
#pragma unroll
        for (int k = 0; k < 16; k++) {
            int idx = tid + k * 256;
            int pl = idx >> 5, ci = idx & 31;
            float f = S[pl][ci];
            __nv_bfloat16 hi = __float2bfloat16(f);
            size_t o = outbase + (size_t)pl * 512 + ci0 + ci;
            g_Ah[o] = hi;
            g_Al[o] = __float2bfloat16(f - __bfloat162float(hi));
        }
    }
}

// ---------------------------------------------------------------------------
__device__ __forceinline__ void load_stage(uint32_t sb, int conv, int p0, int c0, int s, int tid) {
    const int tap = c_taps[conv][s >> 3];
    const int ci0 = (s & 7) << 6;
    const uint32_t stage = sb + (uint32_t)(s & 1) * STAGEB;
#pragma unroll
    for (int k = 0; k < 16; k++) {
        int i = tid + k * 256;
        int tile = i >> 10;          // uniform per k
        int rem = i & 1023;
        int row = rem >> 3, seg = rem & 7;
        uint32_t dst = stage + tile * TILEB + row * ROWB + seg * 16;
        const __nv_bfloat16* src;
        if (tile < 2)
            src = (tile ? g_Al : g_Ah) + ((size_t)tap * 16384 + p0 + row) * 512 + ci0 + seg * 8;
        else
            src = (tile == 2 ? g_Bh : g_Bl) +
                  ((size_t)(conv * 9 + tap) * 256 + c0 + row) * 512 + ci0 + seg * 8;
        asm volatile("cp.async.cg.shared.global [%0], [%1], 16;" :: "r"(dst), "l"(src));
    }
}

__global__ __launch_bounds__(256, 1)
void conv_mma(const float* __restrict__ b1, const float* __restrict__ b2,
              const float* __restrict__ b3, const float* __restrict__ b4) {
    extern __shared__ char smem[];
    const uint32_t sb = smem_u32(smem);
    const int tid = threadIdx.x, wid = tid >> 5, lane = tid & 31;
    const int conv = blockIdx.x >> 8;
    const int c0 = ((blockIdx.x >> 7) & 1) * 128;
    const int p0 = (blockIdx.x & 127) * 128;
    const int S = c_ntaps[conv] * 8;

    const int m0 = (wid & 3) * 32;
    const int n0 = (wid >> 2) * 64;

    float d[2][8][4];
#pragma unroll
    for (int mt = 0; mt < 2; mt++)
#pragma unroll
        for (int nt = 0; nt < 8; nt++)
#pragma unroll
            for (int e = 0; e < 4; e++) d[mt][nt][e] = 0.f;

    load_stage(sb, conv, p0, c0, 0, tid);
    asm volatile("cp.async.commit_group;");

    for (int s = 0; s < S; s++) {
        if (s + 1 < S) {
            load_stage(sb, conv, p0, c0, s + 1, tid);
            asm volatile("cp.async.commit_group;");
            asm volatile("cp.async.wait_group 1;");
        } else {
            asm volatile("cp.async.wait_group 0;");
        }
        __syncthreads();

        const uint32_t stage = sb + (uint32_t)(s & 1) * STAGEB;
        uint32_t aH[2][4], aL[2][4], bH[16], bL[16];
#pragma unroll
        for (int kk = 0; kk < 4; kk++) {
            const uint32_t arow = m0 + (lane & 15);
            const uint32_t akof = kk * 32 + ((lane >> 4) << 4);
            uint32_t aa = stage + arow * ROWB + akof;
            ldsm4(aH[0][0], aH[0][1], aH[0][2], aH[0][3], aa);
            ldsm4(aH[1][0], aH[1][1], aH[1][2], aH[1][3], aa + 16 * ROWB);
            ldsm4(aL[0][0], aL[0][1], aL[0][2], aL[0][3], aa + TILEB);
            ldsm4(aL[1][0], aL[1][1], aL[1][2], aL[1][3], aa + TILEB + 16 * ROWB);
            const uint32_t brow = n0 + ((lane >> 4) << 3) + (lane & 7);
            const uint32_t bkof = kk * 32 + (((lane >> 3) & 1) << 4);
#pragma unroll
            for (int bt = 0; bt < 4; bt++) {
                uint32_t ba = stage + 2 * TILEB + (brow + bt * 16) * ROWB + bkof;
                ldsm4(bH[bt * 4], bH[bt * 4 + 1], bH[bt * 4 + 2], bH[bt * 4 + 3], ba);
                ldsm4(bL[bt * 4], bL[bt * 4 + 1], bL[bt * 4 + 2], bL[bt * 4 + 3], ba + TILEB);
            }
#pragma unroll
            for (int mt = 0; mt < 2; mt++)
#pragma unroll
                for (int nt = 0; nt < 8; nt++) {
                    mma_bf16(d[mt][nt], aH[mt], bH[nt * 2], bH[nt * 2 + 1]);
                    mma_bf16(d[mt][nt], aH[mt], bL[nt * 2], bL[nt * 2 + 1]);
                    mma_bf16(d[mt][nt], aL[mt], bH[nt * 2], bH[nt * 2 + 1]);
                }
        }
        __syncthreads();
    }

    // Epilogue: add bias, store to scratch (sector-coalesced along sp)
    const float* bias = (conv == 0) ? b1 : (conv == 1) ? b2 : (conv == 2) ? b3 : b4;
#pragma unroll
    for (int mt = 0; mt < 2; mt++)
#pragma unroll
        for (int nt = 0; nt < 8; nt++) {
            int prow = p0 + m0 + mt * 16 + (lane >> 2);
            int co = c0 + n0 + nt * 8 + (lane & 3) * 2;
            float bv0 = __ldg(bias + co), bv1 = __ldg(bias + co + 1);
            size_t base = ((size_t)(conv * NB + (prow >> 10)) * COUT + co) * 1024 + (prow & 1023);
            g_scratch[base]            = d[mt][nt][0] + bv0;
            g_scratch[base + 1024]     = d[mt][nt][1] + bv1;
            g_scratch[base + 8]        = d[mt][nt][2] + bv0;
            g_scratch[base + 1024 + 8] = d[mt][nt][3] + bv1;
        }
}

// BN stats: one block per channel, deterministic tree reduction
__global__ void stats_k(const float* __restrict__ gamma, const float* __restrict__ beta) {
    __shared__ float sS[256], sQ[256];
    const int c = blockIdx.x, tid = threadIdx.x;
    float S = 0.f, Q = 0.f;
    for (int idx = tid; idx < 65536; idx += 256) {
        int sp = idx & 1023, cn = idx >> 10;
        float v = g_scratch[((size_t)cn * COUT + c) * 1024 + sp];
        S += v; Q += v * v;
    }
    sS[tid] = S; sQ[tid] = Q;
    __syncthreads();
    for (int off = 128; off > 0; off >>= 1) {
        if (tid < off) { sS[tid] += sS[tid + off]; sQ[tid] += sQ[tid + off]; }
        __syncthreads();
    }
    if (tid == 0) {
        const float inv = 1.f / 65536.f;
        float mean = sS[0] * inv;
        float var = sQ[0] * inv - mean * mean;
        float sc = gamma[c] * rsqrtf(var + EPSV);
        g_scale[c] = sc;
        g_shift[c] = beta[c] - mean * sc;
    }
}

__global__ void apply_k(float* __restrict__ out) {
    int t = blockIdx.x * blockDim.x + threadIdx.x;
    int base = t * 4;
    if (base >= NB * COUT * 64 * 64) return;
    int J0 = base & 63, I = (base >> 6) & 63, c = (base >> 12) & 255, n = base >> 20;
    int i = I >> 1, pr = I & 1;
    float sc = g_scale[c], sh = g_shift[c];
    float v[4];
#pragma unroll
    for (int e = 0; e < 4; e++) {
        int J = J0 + e;
        int conv = pr + ((J & 1) << 1);
        int j = J >> 1;
        float o = g_scratch[((((size_t)conv * NB + n) * COUT + c) * HH + i) * WW + j];
        float y = o * sc + sh;
        v[e] = y > 0.f ? y : 0.f;
    }
    *(float4*)(out + base) = make_float4(v[0], v[1], v[2], v[3]);
}

extern "C" void kernel_launch(void* const* d_in, const int* in_sizes, int n_in,
                              void* d_out, int out_size) {
    const float* x     = (const float*)d_in[0];
    const float* w1    = (const float*)d_in[1];
    const float* b1    = (const float*)d_in[2];
    const float* w2    = (const float*)d_in[3];
    const float* b2    = (const float*)d_in[4];
    const float* w3    = (const float*)d_in[5];
    const float* b3    = (const float*)d_in[6];
    const float* w4    = (const float*)d_in[7];
    const float* b4    = (const float*)d_in[8];
    const float* gamma = (const float*)d_in[9];
    const float* beta  = (const float*)d_in[10];
    float* out = (float*)d_out;

    cudaFuncSetAttribute(conv_mma, cudaFuncAttributeMaxDynamicSharedMemorySize, SMEM_SZ);
    prep_w<<<2048, 256>>>(w1, w2, w3, w4);
    prep_a<<<dim3(8, 16, 9), 256>>>(x);
    conv_mma<<<1024, 256, SMEM_SZ>>>(b1, b2, b3, b4);
    stats_k<<<COUT, 256>>>(gamma, beta);
    apply_k<<<(NB * COUT * 64 * 64 / 4 + 255) / 256, 256>>>(out);
}